// round 16
// baseline (speedup 1.0000x reference)
#include <cuda_runtime.h>
#include <cuda_fp16.h>
#include <cstdint>

#define Bz 8
#define L0c 384
#define Lr 385
#define LP 448
#define Dm 128
#define NH 8
#define NIT 4
#define RS 10   // half2 row stride (slots 0..7 + pad)

// ---------------- scratch (all fp32, R2 layouts) ----------------
__device__ float g_unary[Bz*LP*Dm];
__device__ float g_qz[Bz*LP*Dm];
__device__ float g_P[(Bz*LP + 128)*Dm];
__device__ float g_m1[Bz*LP];
__device__ float g_Tu[2*Dm*NH*Dm];        // [k][a][c][b]
__device__ float g_Tv[2*Dm*NH*Dm];        // [k][b][c][a]
__device__ float g_U[Bz*2*LP*NH*Dm];      // stacked m=(i*8+c)
__device__ float g_V[Bz*2*LP*NH*Dm];
__device__ float g_Hmat[(size_t)Bz*NH*LP*LP];
__device__ float g_Gp[Bz*NH*LP*Dm];
__device__ float g_Hp[Bz*NH*LP*Dm];

// ---------------- fp16 split helpers ----------------
__device__ __forceinline__ void split2h(float x, __half& h, __half& l) {
    h = __float2half_rn(x);
    l = __float2half_rn(x - __half2float(h));
}
__device__ __forceinline__ void mmah(float* c, const unsigned* a, const unsigned* b) {
    asm volatile(
        "mma.sync.aligned.m16n8k16.row.col.f32.f16.f16.f32 "
        "{%0,%1,%2,%3}, {%4,%5,%6,%7}, {%8,%9}, {%0,%1,%2,%3};"
        : "+f"(c[0]), "+f"(c[1]), "+f"(c[2]), "+f"(c[3])
        : "r"(a[0]), "r"(a[1]), "r"(a[2]), "r"(a[3]), "r"(b[0]), "r"(b[1]));
}
__device__ __forceinline__ __half2 mkh2(__half a, __half b) { __half2 r; r.x = a; r.y = b; return r; }
__device__ __forceinline__ int slot8(int kp) { return (kp & 3)*2 + (kp >> 2); }

// fragment loaders (paired-slot layout)
#define FRAG_A(dsth, dstl, SH, SL, buf, rbase) do { \
    uint2 _va = *(const uint2*)&SH[buf][(rbase)*RS + 2*gc]; \
    uint2 _vb = *(const uint2*)&SH[buf][(rbase + 8)*RS + 2*gc]; \
    dsth[0] = _va.x; dsth[1] = _vb.x; dsth[2] = _va.y; dsth[3] = _vb.y; \
    uint2 _wa = *(const uint2*)&SL[buf][(rbase)*RS + 2*gc]; \
    uint2 _wb = *(const uint2*)&SL[buf][(rbase + 8)*RS + 2*gc]; \
    dstl[0] = _wa.x; dstl[1] = _wb.x; dstl[2] = _wa.y; dstl[3] = _wb.y; \
} while (0)
#define FRAG_B(dsth, dstl, SH, SL, buf, cbase) do { \
    uint2 _v = *(const uint2*)&SH[buf][(cbase)*RS + 2*gc]; \
    dsth[0] = _v.x; dsth[1] = _v.y; \
    uint2 _w = *(const uint2*)&SL[buf][(cbase)*RS + 2*gc]; \
    dstl[0] = _w.x; dstl[1] = _w.y; \
} while (0)

// ---------------- prep ----------------
__global__ void prep_unary_kernel(const float* __restrict__ x,
                                  const float* __restrict__ mask) {
    int idx = blockIdx.x * blockDim.x + threadIdx.x;
    if (idx >= Bz*LP*Dm) return;
    int d = idx & 127;
    int zi = idx >> 7;
    int i = zi % LP, z = zi / LP;
    float v = 0.f;
    if (i >= 1 && i < Lr) v = x[(z*L0c + (i-1))*Dm + d];
    float m = (i == 0) ? 1.f : ((i < Lr) ? mask[z*L0c + (i-1)] : 0.f);
    g_unary[idx] = v;
    g_qz[idx]    = v * m;
    g_P[idx]     = 0.f;
    if (d == 0) g_m1[zi] = m;
}

__global__ void zero_ppad_kernel() {
    int idx = blockIdx.x * blockDim.x + threadIdx.x;
    if (idx < 128*Dm) g_P[Bz*LP*Dm + idx] = 0.f;
}

__global__ void prep_T_kernel(const float* __restrict__ tern) {
    int idx = blockIdx.x * blockDim.x + threadIdx.x;
    if (idx >= 2*Dm*Dm*NH) return;
    int c = idx & 7;
    int r = idx >> 3;
    int b = r & 127; r >>= 7;
    int a = r & 127;
    int k = r >> 7;
    float v = tern[idx];
    g_Tu[((k*Dm + a)*NH + c)*Dm + b] = v;
    g_Tv[((k*Dm + b)*NH + c)*Dm + a] = v;
}

// ---------------- softmax over d ----------------
__global__ void softmax_p_kernel() {
    int row = blockIdx.x;
    int z = row / Lr, i = row - z*Lr;
    const float* src = g_qz + (z*LP + i)*Dm;
    int t = threadIdx.x;
    float v = src[t];
    __shared__ float shm[4], shs[4];
    float m = v;
#pragma unroll
    for (int o = 16; o; o >>= 1) m = fmaxf(m, __shfl_xor_sync(0xffffffffu, m, o));
    if ((t & 31) == 0) shm[t >> 5] = m;
    __syncthreads();
    m = fmaxf(fmaxf(shm[0], shm[1]), fmaxf(shm[2], shm[3]));
    float e = __expf(v - m);
    float s = e;
#pragma unroll
    for (int o = 16; o; o >>= 1) s += __shfl_xor_sync(0xffffffffu, s, o);
    if ((t & 31) == 0) shs[t >> 5] = s;
    __syncthreads();
    s = (shs[0] + shs[1]) + (shs[2] + shs[3]);
    g_P[(z*LP + i)*Dm + t] = e / s * g_m1[z*LP + i];
}

// =============== UV (fp16 3-term, DB, paired slots): C[448x1024] = P @ T ===============
__global__ __launch_bounds__(256) void gemm_uv_kernel() {
    __shared__ __half2 Ah2[2][64*RS],  Al2[2][64*RS];
    __shared__ __half2 Bh2[2][128*RS], Bl2[2][128*RS];
    int inst = blockIdx.z;
    int uv = inst & 1, kg = (inst >> 1) & 1, z = inst >> 2;
    const float* A  = g_P + (size_t)(z*LP)*Dm;
    const float* Bm = (uv ? g_Tv : g_Tu) + kg * (Dm*NH*Dm);
    float*       C  = (uv ? g_V : g_U) + (size_t)(z*2 + kg) * (LP*NH*Dm);
    int m0 = blockIdx.y * 64, n0 = blockIdx.x * 128;
    int t = threadIdx.x, lane = t & 31, warp = t >> 5;
    int wm = (warp >> 2)*32, wn = (warp & 3)*32;
    int gr = lane >> 2, gc = lane & 3;
    int ar = t >> 2, aq = (t & 3) << 2;
    int kp = t >> 5, bn = lane << 2;
    int bsl = slot8(kp);
    float acc[2][4][4] = {};
    float4 pa, pr0, pr1;
    pa  = *(const float4*)&A[(size_t)(m0 + ar)*Dm + aq];
    pr0 = *(const float4*)&Bm[(size_t)(2*kp)*1024 + n0 + bn];
    pr1 = *(const float4*)&Bm[(size_t)(2*kp + 1)*1024 + n0 + bn];
    {
        float pv[4] = {pa.x, pa.y, pa.z, pa.w};
#pragma unroll
        for (int q = 0; q < 2; q++) {
            int sl = slot8((aq>>1)+q);
            __half h0,l0,h1,l1;
            split2h(pv[2*q], h0, l0); split2h(pv[2*q+1], h1, l1);
            Ah2[0][ar*RS + sl] = mkh2(h0, h1);
            Al2[0][ar*RS + sl] = mkh2(l0, l1);
        }
        float v0[4] = {pr0.x,pr0.y,pr0.z,pr0.w};
        float v1[4] = {pr1.x,pr1.y,pr1.z,pr1.w};
#pragma unroll
        for (int q = 0; q < 4; q++) {
            __half h0,l0,h1,l1;
            split2h(v0[q], h0, l0); split2h(v1[q], h1, l1);
            Bh2[0][(bn+q)*RS + bsl] = mkh2(h0, h1);
            Bl2[0][(bn+q)*RS + bsl] = mkh2(l0, l1);
        }
    }
    __syncthreads();
    for (int s = 0; s < 8; s++) {
        int cb = s & 1, nb = cb ^ 1;
        if (s < 7) {
            int k1 = (s + 1) << 4;
            pa  = *(const float4*)&A[(size_t)(m0 + ar)*Dm + k1 + aq];
            pr0 = *(const float4*)&Bm[(size_t)(k1 + 2*kp)*1024 + n0 + bn];
            pr1 = *(const float4*)&Bm[(size_t)(k1 + 2*kp + 1)*1024 + n0 + bn];
        }
        unsigned ah[2][4], al_[2][4], bh[4][2], bl_[4][2];
#pragma unroll
        for (int tm = 0; tm < 2; tm++) FRAG_A(ah[tm], al_[tm], Ah2, Al2, cb, wm + tm*16 + gr);
#pragma unroll
        for (int tn = 0; tn < 4; tn++) FRAG_B(bh[tn], bl_[tn], Bh2, Bl2, cb, wn + tn*8 + gr);
#pragma unroll
        for (int tm = 0; tm < 2; tm++)
#pragma unroll
            for (int tn = 0; tn < 4; tn++) {
                mmah(acc[tm][tn], al_[tm], bh[tn]);
                mmah(acc[tm][tn], ah[tm], bl_[tn]);
                mmah(acc[tm][tn], ah[tm], bh[tn]);
            }
        if (s < 7) {
            float pv[4] = {pa.x, pa.y, pa.z, pa.w};
#pragma unroll
            for (int q = 0; q < 2; q++) {
                int sl = slot8((aq>>1)+q);
                __half h0,l0,h1,l1;
                split2h(pv[2*q], h0, l0); split2h(pv[2*q+1], h1, l1);
                Ah2[nb][ar*RS + sl] = mkh2(h0, h1);
                Al2[nb][ar*RS + sl] = mkh2(l0, l1);
            }
            float v0[4] = {pr0.x,pr0.y,pr0.z,pr0.w};
            float v1[4] = {pr1.x,pr1.y,pr1.z,pr1.w};
#pragma unroll
            for (int q = 0; q < 4; q++) {
                __half h0,l0,h1,l1;
                split2h(v0[q], h0, l0); split2h(v1[q], h1, l1);
                Bh2[nb][(bn+q)*RS + bsl] = mkh2(h0, h1);
                Bl2[nb][(bn+q)*RS + bsl] = mkh2(l0, l1);
            }
        }
        __syncthreads();
    }
#pragma unroll
    for (int tm = 0; tm < 2; tm++)
#pragma unroll
        for (int tn = 0; tn < 4; tn++) {
            int r  = m0 + wm + tm*16 + gr;
            int cn = n0 + wn + tn*8 + 2*gc;
            float2 w0; w0.x = acc[tm][tn][0]; w0.y = acc[tm][tn][1];
            float2 w1; w1.x = acc[tm][tn][2]; w1.y = acc[tm][tn][3];
            *(float2*)&C[(size_t)r*1024 + cn]     = w0;
            *(float2*)&C[(size_t)(r+8)*1024 + cn] = w1;
        }
}

// =============== F (fp16 3-term, DB, paired slots): tile 128x64, warps 4x2 ===============
__global__ __launch_bounds__(256) void gemm_f_kernel() {
    __shared__ __half2 Ah2[2][128*RS], Al2[2][128*RS];
    __shared__ __half2 Bh2[2][64*RS],  Bl2[2][64*RS];
    int z = blockIdx.z;
    int m0 = blockIdx.y*128, j0 = blockIdx.x*64;
    int ilo = m0 >> 3;
    int mode = (j0 >= ilo + 16) ? 0 : ((j0 + 64 <= ilo) ? 1 : 2);
    int npass = (mode == 2) ? 2 : 1;
    int t = threadIdx.x, lane = t & 31, warp = t >> 5;
    int wm = (warp >> 1)*32, wn = (warp & 1)*32;
    int gr = lane >> 2, gc = lane & 3;
    int am = t >> 1, ah8 = (t & 1) << 3;
    int jr = t >> 2, bq = (t & 3) << 2;
    const float* Bp = g_P + (size_t)(z*LP)*Dm;
    for (int p = 0; p < npass; p++) {
        int g = (mode == 2) ? p : mode;
        const float* Au = g_U + (size_t)(z*2+g)*(LP*NH*Dm);
        float acc[2][4][4] = {};
        float4 a0, a1, b0;
        a0 = *(const float4*)&Au[(size_t)(m0+am)*Dm + ah8];
        a1 = *(const float4*)&Au[(size_t)(m0+am)*Dm + ah8 + 4];
        b0 = *(const float4*)&Bp[(size_t)(j0+jr)*Dm + bq];
        {
            float av[8] = {a0.x,a0.y,a0.z,a0.w,a1.x,a1.y,a1.z,a1.w};
#pragma unroll
            for (int q = 0; q < 4; q++) {
                int sl = slot8((ah8>>1)+q);
                __half h0,l0,h1,l1;
                split2h(av[2*q], h0, l0); split2h(av[2*q+1], h1, l1);
                Ah2[0][am*RS + sl] = mkh2(h0, h1);
                Al2[0][am*RS + sl] = mkh2(l0, l1);
            }
            float bv[4] = {b0.x,b0.y,b0.z,b0.w};
#pragma unroll
            for (int q = 0; q < 2; q++) {
                int sl = slot8((bq>>1)+q);
                __half h0,l0,h1,l1;
                split2h(bv[2*q], h0, l0); split2h(bv[2*q+1], h1, l1);
                Bh2[0][jr*RS + sl] = mkh2(h0, h1);
                Bl2[0][jr*RS + sl] = mkh2(l0, l1);
            }
        }
        __syncthreads();
        for (int s = 0; s < 8; s++) {
            int cb = s & 1, nb = cb ^ 1;
            if (s < 7) {
                int k1 = (s + 1) << 4;
                a0 = *(const float4*)&Au[(size_t)(m0+am)*Dm + k1 + ah8];
                a1 = *(const float4*)&Au[(size_t)(m0+am)*Dm + k1 + ah8 + 4];
                b0 = *(const float4*)&Bp[(size_t)(j0+jr)*Dm + k1 + bq];
            }
            unsigned ah[2][4], al_[2][4], bh[4][2], bl_[4][2];
#pragma unroll
            for (int tm = 0; tm < 2; tm++) FRAG_A(ah[tm], al_[tm], Ah2, Al2, cb, wm + tm*16 + gr);
#pragma unroll
            for (int tn = 0; tn < 4; tn++) FRAG_B(bh[tn], bl_[tn], Bh2, Bl2, cb, wn + tn*8 + gr);
#pragma unroll
            for (int tm = 0; tm < 2; tm++)
#pragma unroll
                for (int tn = 0; tn < 4; tn++) {
                    mmah(acc[tm][tn], al_[tm], bh[tn]);
                    mmah(acc[tm][tn], ah[tm], bl_[tn]);
                    mmah(acc[tm][tn], ah[tm], bh[tn]);
                }
            if (s < 7) {
                float av[8] = {a0.x,a0.y,a0.z,a0.w,a1.x,a1.y,a1.z,a1.w};
#pragma unroll
                for (int q = 0; q < 4; q++) {
                    int sl = slot8((ah8>>1)+q);
                    __half h0,l0,h1,l1;
                    split2h(av[2*q], h0, l0); split2h(av[2*q+1], h1, l1);
                    Ah2[nb][am*RS + sl] = mkh2(h0, h1);
                    Al2[nb][am*RS + sl] = mkh2(l0, l1);
                }
                float bv[4] = {b0.x,b0.y,b0.z,b0.w};
#pragma unroll
                for (int q = 0; q < 2; q++) {
                    int sl = slot8((bq>>1)+q);
                    __half h0,l0,h1,l1;
                    split2h(bv[2*q], h0, l0); split2h(bv[2*q+1], h1, l1);
                    Bh2[nb][jr*RS + sl] = mkh2(h0, h1);
                    Bl2[nb][jr*RS + sl] = mkh2(l0, l1);
                }
            }
            __syncthreads();
        }
#pragma unroll
        for (int tm = 0; tm < 2; tm++)
#pragma unroll
            for (int tn = 0; tn < 4; tn++) {
                int jc = j0 + wn + tn*8 + 2*gc;
#pragma unroll
                for (int half = 0; half < 2; half++) {
                    int m = m0 + wm + tm*16 + gr + half*8;
                    int i = m >> 3, cc = m & 7;
                    size_t off = ((size_t)(z*NH + cc)*LP + i)*LP + jc;
                    float v0 = acc[tm][tn][half*2], v1 = acc[tm][tn][half*2 + 1];
                    if (mode != 2) {
                        float2 w; w.x = v0; w.y = v1;
                        *(float2*)&g_Hmat[off] = w;
                    } else if (p == 0) {
                        float2 w;
                        w.x = (jc     > i) ? v0 : 0.f;
                        w.y = (jc + 1 > i) ? v1 : 0.f;
                        *(float2*)&g_Hmat[off] = w;
                    } else {
                        if (jc     < i) g_Hmat[off]     = v0;
                        if (jc + 1 < i) g_Hmat[off + 1] = v1;
                    }
                }
            }
    }
}

// ---------------- H softmax over j ----------------
__global__ void hsoftmax_kernel() {
    int bid = blockIdx.x;
    int i = bid % Lr;
    int zc = bid / Lr;
    int z = zc >> 3;
    float* row = g_Hmat + (size_t)zc * (LP*LP) + (size_t)i * LP;
    int t = threadIdx.x;
    if (i == 0) {
        for (int j = t; j < Lr; j += 128) row[j] = 0.f;
        return;
    }
    float mi = g_m1[z*LP + i];
    float lv[4];
    float mx = -3.4e38f;
#pragma unroll
    for (int r = 0; r < 4; r++) {
        int j = t + r*128;
        float l = -3.4e38f;
        if (j < Lr) {
            bool ok = (mi != 0.f) && (g_m1[z*LP + j] != 0.f) && (j != i);
            l = ok ? row[j] * 128.f : -1e9f;
        }
        lv[r] = l;
        mx = fmaxf(mx, l);
    }
    __shared__ float shm[4], shs[4];
#pragma unroll
    for (int o = 16; o; o >>= 1) mx = fmaxf(mx, __shfl_xor_sync(0xffffffffu, mx, o));
    if ((t & 31) == 0) shm[t >> 5] = mx;
    __syncthreads();
    mx = fmaxf(fmaxf(shm[0], shm[1]), fmaxf(shm[2], shm[3]));
    float ev[4];
    float s = 0.f;
#pragma unroll
    for (int r = 0; r < 4; r++) {
        int j = t + r*128;
        ev[r] = 0.f;
        if (j < Lr) { ev[r] = __expf(lv[r] - mx); s += ev[r]; }
    }
#pragma unroll
    for (int o = 16; o; o >>= 1) s += __shfl_xor_sync(0xffffffffu, s, o);
    if ((t & 31) == 0) shs[t >> 5] = s;
    __syncthreads();
    s = (shs[0] + shs[1]) + (shs[2] + shs[3]);
    float inv = 1.f / s;
#pragma unroll
    for (int r = 0; r < 4; r++) {
        int j = t + r*128;
        if (j < Lr) row[j] = ev[r] * inv;
    }
}

// =============== G (fp16 3-term, DB, paired slots, 32 flat stages) ===============
__global__ __launch_bounds__(256) void gemm_g_kernel() {
    __shared__ __half2 Ah2[2][64*RS],  Al2[2][64*RS];
    __shared__ __half2 Bh2[2][128*RS], Bl2[2][128*RS];
    int c = blockIdx.x, i0 = blockIdx.y*64, z = blockIdx.z;
    const float* Hmp = g_Hmat + (size_t)(z*NH + c)*(LP*LP);
    int t = threadIdx.x, lane = t & 31, warp = t >> 5;
    int wm = (warp >> 2)*32, wn = (warp & 3)*32;
    int gr = lane >> 2, gc = lane & 3;
    int ir = t >> 2, jq = (t & 3) << 2;
    int jp = t >> 5, bn = lane << 2;
    int bsl = slot8(jp);
    int c0 = i0 >> 4;
    float acc[2][4][4] = {};
    float4 hv; float4 v0, v1;
    int nss, np, nmode;
#define G_MAP(f, ss, p, md) \
    if ((f) < c0) { ss = (f); p = 0; md = 1; } \
    else if ((f) < c0 + 8) { ss = c0 + (((f) - c0) >> 1); p = ((f) - c0) & 1; md = 2; } \
    else { ss = (f) - 4; p = 0; md = 0; }
    {
        G_MAP(0, nss, np, nmode)
        int gg = (nmode == 2) ? np : nmode;
        int j0s = nss << 4;
        hv = *(const float4*)&Hmp[(size_t)(i0 + ir)*LP + j0s + jq];
        const float* Vp = g_V + (size_t)(z*2+gg)*(LP*NH*Dm) + (size_t)c*Dm;
        v0 = *(const float4*)&Vp[(size_t)(j0s + 2*jp)*1024 + bn];
        v1 = *(const float4*)&Vp[(size_t)(j0s + 2*jp + 1)*1024 + bn];
        int ig = i0 + ir;
        float h4[4] = {hv.x, hv.y, hv.z, hv.w};
        float mv[4];
#pragma unroll
        for (int q = 0; q < 4; q++) {
            float val = h4[q];
            if (nmode == 2) {
                int jg = j0s + jq + q;
                bool keep = (gg == 0) ? (jg > ig) : (jg < ig);
                if (!keep) val = 0.f;
            }
            mv[q] = val;
        }
#pragma unroll
        for (int q = 0; q < 2; q++) {
            int sl = slot8((jq>>1)+q);
            __half h0,l0,h1,l1;
            split2h(mv[2*q], h0, l0); split2h(mv[2*q+1], h1, l1);
            Ah2[0][ir*RS + sl] = mkh2(h0, h1);
            Al2[0][ir*RS + sl] = mkh2(l0, l1);
        }
        float r0[4] = {v0.x,v0.y,v0.z,v0.w};
        float r1[4] = {v1.x,v1.y,v1.z,v1.w};
#pragma unroll
        for (int q = 0; q < 4; q++) {
            __half h0,l0,h1,l1;
            split2h(r0[q], h0, l0); split2h(r1[q], h1, l1);
            Bh2[0][(bn+q)*RS + bsl] = mkh2(h0, h1);
            Bl2[0][(bn+q)*RS + bsl] = mkh2(l0, l1);
        }
    }
    __syncthreads();
    for (int f = 0; f < 32; f++) {
        int cb = f & 1, nb = cb ^ 1;
        int gg = 0, j0s = 0;
        if (f + 1 < 32) {
            G_MAP(f + 1, nss, np, nmode)
            gg = (nmode == 2) ? np : nmode;
            j0s = nss << 4;
            hv = *(const float4*)&Hmp[(size_t)(i0 + ir)*LP + j0s + jq];
            const float* Vp = g_V + (size_t)(z*2+gg)*(LP*NH*Dm) + (size_t)c*Dm;
            v0 = *(const float4*)&Vp[(size_t)(j0s + 2*jp)*1024 + bn];
            v1 = *(const float4*)&Vp[(size_t)(j0s + 2*jp + 1)*1024 + bn];
        }
        unsigned ah[2][4], al_[2][4], bh[4][2], bl_[4][2];
#pragma unroll
        for (int tm = 0; tm < 2; tm++) FRAG_A(ah[tm], al_[tm], Ah2, Al2, cb, wm + tm*16 + gr);
#pragma unroll
        for (int tn = 0; tn < 4; tn++) FRAG_B(bh[tn], bl_[tn], Bh2, Bl2, cb, wn + tn*8 + gr);
#pragma unroll
        for (int tm = 0; tm < 2; tm++)
#pragma unroll
            for (int tn = 0; tn < 4; tn++) {
                mmah(acc[tm][tn], al_[tm], bh[tn]);
                mmah(acc[tm][tn], ah[tm], bl_[tn]);
                mmah(acc[tm][tn], ah[tm], bh[tn]);
            }
        if (f + 1 < 32) {
            int ig = i0 + ir;
            float h4[4] = {hv.x, hv.y, hv.z, hv.w};
            float mv[4];
#pragma unroll
            for (int q = 0; q < 4; q++) {
                float val = h4[q];
                if (nmode == 2) {
                    int jg = j0s + jq + q;
                    bool keep = (gg == 0) ? (jg > ig) : (jg < ig);
                    if (!keep) val = 0.f;
                }
                mv[q] = val;
            }
#pragma unroll
            for (int q = 0; q < 2; q++) {
                int sl = slot8((jq>>1)+q);
                __half h0,l0,h1,l1;
                split2h(mv[2*q], h0, l0); split2h(mv[2*q+1], h1, l1);
                Ah2[nb][ir*RS + sl] = mkh2(h0, h1);
                Al2[nb][ir*RS + sl] = mkh2(l0, l1);
            }
            float r0[4] = {v0.x,v0.y,v0.z,v0.w};
            float r1[4] = {v1.x,v1.y,v1.z,v1.w};
#pragma unroll
            for (int q = 0; q < 4; q++) {
                __half h0,l0,h1,l1;
                split2h(r0[q], h0, l0); split2h(r1[q], h1, l1);
                Bh2[nb][(bn+q)*RS + bsl] = mkh2(h0, h1);
                Bl2[nb][(bn+q)*RS + bsl] = mkh2(l0, l1);
            }
        }
        __syncthreads();
    }
#undef G_MAP
    float* out = &g_Gp[((size_t)(z*NH + c)*LP + i0)*Dm];
#pragma unroll
    for (int tm = 0; tm < 2; tm++)
#pragma unroll
        for (int tn = 0; tn < 4; tn++) {
            int r  = wm + tm*16 + gr;
            int cn = wn + tn*8 + 2*gc;
            float2 w0; w0.x = acc[tm][tn][0]; w0.y = acc[tm][tn][1];
            float2 w1; w1.x = acc[tm][tn][2]; w1.y = acc[tm][tn][3];
            *(float2*)&out[(size_t)r*Dm + cn]     = w0;
            *(float2*)&out[(size_t)(r+8)*Dm + cn] = w1;
        }
}

// =============== Hm (fp16 3-term, DB, paired slots, 32 flat stages) ===============
__global__ __launch_bounds__(256) void gemm_hm_kernel() {
    __shared__ __half2 Ah2[2][64*RS],  Al2[2][64*RS];
    __shared__ __half2 Bh2[2][128*RS], Bl2[2][128*RS];
    int c = blockIdx.x, j0 = blockIdx.y*64, z = blockIdx.z;
    const float* Hmp = g_Hmat + (size_t)(z*NH + c)*(LP*LP);
    int t = threadIdx.x, lane = t & 31, warp = t >> 5;
    int wm = (warp >> 2)*32, wn = (warp & 3)*32;
    int gr = lane >> 2, gc = lane & 3;
    int ip = t >> 5, jc2 = lane << 1;
    int bn = lane << 2;
    int asl = slot8(ip);
    int c0 = j0 >> 4;
    float acc[2][4][4] = {};
    float2 hr0, hr1; float4 u0, u1;
    int nss, np, nmode;
#define H_MAP(f, ss, p, md) \
    if ((f) < c0) { ss = (f); p = 0; md = 0; } \
    else if ((f) < c0 + 8) { ss = c0 + (((f) - c0) >> 1); p = ((f) - c0) & 1; md = 2; } \
    else { ss = (f) - 4; p = 0; md = 1; }
    {
        H_MAP(0, nss, np, nmode)
        int gg = (nmode == 2) ? np : nmode;
        int i0s = nss << 4;
        int ig0 = i0s + 2*ip, ig1 = ig0 + 1;
        hr0 = *(const float2*)&Hmp[(size_t)ig0*LP + j0 + jc2];
        hr1 = *(const float2*)&Hmp[(size_t)ig1*LP + j0 + jc2];
        const float* Up = g_U + (size_t)(z*2+gg)*(LP*NH*Dm) + (size_t)c*Dm;
        u0 = *(const float4*)&Up[(size_t)(i0s + 2*ip)*1024 + bn];
        u1 = *(const float4*)&Up[(size_t)(i0s + 2*ip + 1)*1024 + bn];
        float a00 = hr0.x, a01 = hr0.y, a10 = hr1.x, a11 = hr1.y;
        if (nmode == 2) {
            int jg0 = j0 + jc2, jg1 = jg0 + 1;
            if (!((gg == 0) ? (ig0 < jg0) : (ig0 > jg0))) a00 = 0.f;
            if (!((gg == 0) ? (ig0 < jg1) : (ig0 > jg1))) a01 = 0.f;
            if (!((gg == 0) ? (ig1 < jg0) : (ig1 > jg0))) a10 = 0.f;
            if (!((gg == 0) ? (ig1 < jg1) : (ig1 > jg1))) a11 = 0.f;
        }
        __half h00,l00,h01,l01,h10,l10,h11,l11;
        split2h(a00, h00, l00); split2h(a01, h01, l01);
        split2h(a10, h10, l10); split2h(a11, h11, l11);
        Ah2[0][jc2*RS + asl]       = mkh2(h00, h10);
        Ah2[0][(jc2+1)*RS + asl]   = mkh2(h01, h11);
        Al2[0][jc2*RS + asl]       = mkh2(l00, l10);
        Al2[0][(jc2+1)*RS + asl]   = mkh2(l01, l11);
        float r0[4] = {u0.x,u0.y,u0.z,u0.w};
        float r1[4] = {u1.x,u1.y,u1.z,u1.w};
#pragma unroll
        for (int q = 0; q < 4; q++) {
            __half h0,l0,h1,l1;
            split2h(r0[q], h0, l0); split2h(r1[q], h1, l1);
            Bh2[0][(bn+q)*RS + asl] = mkh2(h0, h1);
            Bl2[0][(bn+q)*RS + asl] = mkh2(l0, l1);
        }
    }
    __syncthreads();
    for (int f = 0; f < 32; f++) {
        int cb = f & 1, nb = cb ^ 1;
        int gg = 0, i0s = 0;
        if (f + 1 < 32) {
            H_MAP(f + 1, nss, np, nmode)
            gg = (nmode == 2) ? np : nmode;
            i0s = nss << 4;
            int ig0 = i0s + 2*ip, ig1 = ig0 + 1;
            hr0 = *(const float2*)&Hmp[(size_t)ig0*LP + j0 + jc2];
            hr1 = *(const float2*)&Hmp[(size_t)ig1*LP + j0 + jc2];
            const float* Up = g_U + (size_t)(z*2+gg)*(LP*NH*Dm) + (size_t)c*Dm;
            u0 = *(const float4*)&Up[(size_t)(i0s + 2*ip)*1024 + bn];
            u1 = *(const float4*)&Up[(size_t)(i0s + 2*ip + 1)*1024 + bn];
        }
        unsigned ah[2][4], al_[2][4], bh[4][2], bl_[4][2];
#pragma unroll
        for (int tm = 0; tm < 2; tm++) FRAG_A(ah[tm], al_[tm], Ah2, Al2, cb, wm + tm*16 + gr);
#pragma unroll
        for (int tn = 0; tn < 4; tn++) FRAG_B(bh[tn], bl_[tn], Bh2, Bl2, cb, wn + tn*8 + gr);
#pragma unroll
        for (int tm = 0; tm < 2; tm++)
#pragma unroll
            for (int tn = 0; tn < 4; tn++) {
                mmah(acc[tm][tn], al_[tm], bh[tn]);
                mmah(acc[tm][tn], ah[tm], bl_[tn]);
                mmah(acc[tm][tn], ah[tm], bh[tn]);
            }
        if (f + 1 < 32) {
            int ig0 = i0s + 2*ip, ig1 = ig0 + 1;
            float a00 = hr0.x, a01 = hr0.y, a10 = hr1.x, a11 = hr1.y;
            if (nmode == 2) {
                int jg0 = j0 + jc2, jg1 = jg0 + 1;
                if (!((gg == 0) ? (ig0 < jg0) : (ig0 > jg0))) a00 = 0.f;
                if (!((gg == 0) ? (ig0 < jg1) : (ig0 > jg1))) a01 = 0.f;
                if (!((gg == 0) ? (ig1 < jg0) : (ig1 > jg0))) a10 = 0.f;
                if (!((gg == 0) ? (ig1 < jg1) : (ig1 > jg1))) a11 = 0.f;
            }
            __half h00,l00,h01,l01,h10,l10,h11,l11;
            split2h(a00, h00, l00); split2h(a01, h01, l01);
            split2h(a10, h10, l10); split2h(a11, h11, l11);
            Ah2[nb][jc2*RS + asl]     = mkh2(h00, h10);
            Ah2[nb][(jc2+1)*RS + asl] = mkh2(h01, h11);
            Al2[nb][jc2*RS + asl]     = mkh2(l00, l10);
            Al2[nb][(jc2+1)*RS + asl] = mkh2(l01, l11);
            float r0[4] = {u0.x,u0.y,u0.z,u0.w};
            float r1[4] = {u1.x,u1.y,u1.z,u1.w};
#pragma unroll
            for (int q = 0; q < 4; q++) {
                __half h0,l0,h1,l1;
                split2h(r0[q], h0, l0); split2h(r1[q], h1, l1);
                Bh2[nb][(bn+q)*RS + asl] = mkh2(h0, h1);
                Bl2[nb][(bn+q)*RS + asl] = mkh2(l0, l1);
            }
        }
        __syncthreads();
    }
#undef H_MAP
    float* out = &g_Hp[((size_t)(z*NH + c)*LP + j0)*Dm];
#pragma unroll
    for (int tm = 0; tm < 2; tm++)
#pragma unroll
        for (int tn = 0; tn < 4; tn++) {
            int r  = wm + tm*16 + gr;
            int cn = wn + tn*8 + 2*gc;
            float2 w0; w0.x = acc[tm][tn][0]; w0.y = acc[tm][tn][1];
            float2 w1; w1.x = acc[tm][tn][2]; w1.y = acc[tm][tn][3];
            *(float2*)&out[(size_t)r*Dm + cn]     = w0;
            *(float2*)&out[(size_t)(r+8)*Dm + cn] = w1;
        }
}

// ---------------- q_z = (unary + sum_c Gp + sum_c Hp) * m1 ----------------
__global__ void reduce_qz_kernel() {
    int idx = blockIdx.x * blockDim.x + threadIdx.x;
    if (idx >= Bz*LP*Dm) return;
    int d = idx & 127;
    int zi = idx >> 7;
    int i = zi % LP, z = zi / LP;
    float s = g_unary[idx];
#pragma unroll
    for (int c = 0; c < NH; c++) {
        size_t o = ((size_t)(z*NH + c)*LP + i)*Dm + d;
        s += g_Gp[o] + g_Hp[o];
    }
    g_qz[idx] = s * g_m1[zi];
}

__global__ void out_kernel(float* __restrict__ out) {
    int idx = blockIdx.x * blockDim.x + threadIdx.x;
    if (idx >= Bz*L0c*Dm) return;
    int d = idx & 127;
    int zt = idx >> 7;
    int tt = zt % L0c, z = zt / L0c;
    out[idx] = g_qz[(z*LP + 1 + tt)*Dm + d];
}

extern "C" void kernel_launch(void* const* d_in, const int* in_sizes, int n_in,
                              void* d_out, int out_size) {
    const float* x = nullptr;
    const float* mask = nullptr;
    const float* tern = nullptr;
    for (int i = 0; i < n_in; i++) {
        if (in_sizes[i] == Bz*L0c*Dm)       x    = (const float*)d_in[i];
        else if (in_sizes[i] == Bz*L0c)     mask = (const float*)d_in[i];
        else if (in_sizes[i] == 2*Dm*Dm*NH) tern = (const float*)d_in[i];
    }
    if (!x || !mask || !tern) return;

    prep_unary_kernel<<<(Bz*LP*Dm + 255)/256, 256>>>(x, mask);
    zero_ppad_kernel<<<(128*Dm + 255)/256, 256>>>();
    prep_T_kernel<<<(2*Dm*Dm*NH + 255)/256, 256>>>(tern);

    for (int it = 0; it < NIT; it++) {
        softmax_p_kernel<<<Bz*Lr, 128>>>();
        gemm_uv_kernel<<<dim3(8, 7, 32), 256>>>();
        gemm_f_kernel<<<dim3(7, 28, Bz), 256>>>();
        hsoftmax_kernel<<<Bz*NH*Lr, 128>>>();
        gemm_g_kernel<<<dim3(NH, 7, Bz), 256>>>();
        gemm_hm_kernel<<<dim3(NH, 7, Bz), 256>>>();
        reduce_qz_kernel<<<(Bz*LP*Dm + 255)/256, 256>>>();
    }
    out_kernel<<<(Bz*L0c*Dm + 255)/256, 256>>>((float*)d_out);
}

// round 17
// speedup vs baseline: 1.3210x; 1.3210x over previous
#include <cuda_runtime.h>
#include <cuda_fp16.h>
#include <cstdint>

#define Bz 8
#define L0c 384
#define Lr 385
#define LP 448
#define Dm 128
#define NH 8
#define NIT 4

// ---------------- scratch (all fp32, R2 layouts) ----------------
__device__ float g_unary[Bz*LP*Dm];
__device__ float g_qz[Bz*LP*Dm];
__device__ float g_P[(Bz*LP + 128)*Dm];
__device__ float g_m1[Bz*LP];
__device__ float g_Tu[2*Dm*NH*Dm];
__device__ float g_Tv[2*Dm*NH*Dm];
__device__ float g_U[Bz*2*LP*NH*Dm];
__device__ float g_V[Bz*2*LP*NH*Dm];
__device__ float g_Hmat[(size_t)Bz*NH*LP*LP];
__device__ float g_Gp[Bz*NH*LP*Dm];
__device__ float g_Hp[Bz*NH*LP*Dm];

// ---------------- fp16 split helpers ----------------
__device__ __forceinline__ void split2h(float x, __half& h, __half& l) {
    h = __float2half_rn(x);
    l = __float2half_rn(x - __half2float(h));
}
__device__ __forceinline__ void mmah(float* c, const unsigned* a, const unsigned* b) {
    asm volatile(
        "mma.sync.aligned.m16n8k16.row.col.f32.f16.f16.f32 "
        "{%0,%1,%2,%3}, {%4,%5,%6,%7}, {%8,%9}, {%0,%1,%2,%3};"
        : "+f"(c[0]), "+f"(c[1]), "+f"(c[2]), "+f"(c[3])
        : "r"(a[0]), "r"(a[1]), "r"(a[2]), "r"(a[3]), "r"(b[0]), "r"(b[1]));
}
__device__ __forceinline__ __half2 mkh2(__half a, __half b) { __half2 r; r.x = a; r.y = b; return r; }
#define LDU2(p) (*(const unsigned*)(p))

// ---------------- prep ----------------
__global__ void prep_unary_kernel(const float* __restrict__ x,
                                  const float* __restrict__ mask) {
    int idx = blockIdx.x * blockDim.x + threadIdx.x;
    if (idx >= Bz*LP*Dm) return;
    int d = idx & 127;
    int zi = idx >> 7;
    int i = zi % LP, z = zi / LP;
    float v = 0.f;
    if (i >= 1 && i < Lr) v = x[(z*L0c + (i-1))*Dm + d];
    float m = (i == 0) ? 1.f : ((i < Lr) ? mask[z*L0c + (i-1)] : 0.f);
    g_unary[idx] = v;
    g_qz[idx]    = v * m;
    g_P[idx]     = 0.f;
    if (d == 0) g_m1[zi] = m;
}

__global__ void zero_ppad_kernel() {
    int idx = blockIdx.x * blockDim.x + threadIdx.x;
    if (idx < 128*Dm) g_P[Bz*LP*Dm + idx] = 0.f;
}

__global__ void prep_T_kernel(const float* __restrict__ tern) {
    int idx = blockIdx.x * blockDim.x + threadIdx.x;
    if (idx >= 2*Dm*Dm*NH) return;
    int c = idx & 7;
    int r = idx >> 3;
    int b = r & 127; r >>= 7;
    int a = r & 127;
    int k = r >> 7;
    float v = tern[idx];
    g_Tu[((k*Dm + a)*NH + c)*Dm + b] = v;
    g_Tv[((k*Dm + b)*NH + c)*Dm + a] = v;
}

// ---------------- softmax over d (reads g_qz) ----------------
__global__ void softmax_p_kernel() {
    int row = blockIdx.x;
    int z = row / Lr, i = row - z*Lr;
    const float* src = g_qz + (z*LP + i)*Dm;
    int t = threadIdx.x;
    float v = src[t];
    __shared__ float shm[4], shs[4];
    float m = v;
#pragma unroll
    for (int o = 16; o; o >>= 1) m = fmaxf(m, __shfl_xor_sync(0xffffffffu, m, o));
    if ((t & 31) == 0) shm[t >> 5] = m;
    __syncthreads();
    m = fmaxf(fmaxf(shm[0], shm[1]), fmaxf(shm[2], shm[3]));
    float e = __expf(v - m);
    float s = e;
#pragma unroll
    for (int o = 16; o; o >>= 1) s += __shfl_xor_sync(0xffffffffu, s, o);
    if ((t & 31) == 0) shs[t >> 5] = s;
    __syncthreads();
    s = (shs[0] + shs[1]) + (shs[2] + shs[3]);
    g_P[(z*LP + i)*Dm + t] = e / s * g_m1[z*LP + i];
}

// ---------------- fused: qz=(unary+sum G+Hm)*m1, then softmax -> g_P ----------------
__global__ void reduce_softmax_kernel() {
    int row = blockIdx.x;
    int z = row / Lr, i = row - z*Lr;
    int t = threadIdx.x;
    size_t base = (size_t)(z*LP + i)*Dm + t;
    float s0 = g_unary[base];
#pragma unroll
    for (int c = 0; c < NH; c++) {
        size_t o = ((size_t)(z*NH + c)*LP + i)*Dm + t;
        s0 += g_Gp[o] + g_Hp[o];
    }
    float m1v = g_m1[z*LP + i];
    float v = s0 * m1v;
    __shared__ float shm[4], shs[4];
    float m = v;
#pragma unroll
    for (int o = 16; o; o >>= 1) m = fmaxf(m, __shfl_xor_sync(0xffffffffu, m, o));
    if ((t & 31) == 0) shm[t >> 5] = m;
    __syncthreads();
    m = fmaxf(fmaxf(shm[0], shm[1]), fmaxf(shm[2], shm[3]));
    float e = __expf(v - m);
    float s = e;
#pragma unroll
    for (int o = 16; o; o >>= 1) s += __shfl_xor_sync(0xffffffffu, s, o);
    if ((t & 31) == 0) shs[t >> 5] = s;
    __syncthreads();
    s = (shs[0] + shs[1]) + (shs[2] + shs[3]);
    g_P[base] = e / s * m1v;
}

// =============== UV (fp16 3-term, double-buffered): C[448x1024] = P @ T ===============
__global__ __launch_bounds__(256) void gemm_uv_kernel() {
    __shared__ __half2 Ah2[2][8*72],  Al2[2][8*72];
    __shared__ __half2 Bh2[2][8*136], Bl2[2][8*136];
    int inst = blockIdx.z;
    int uv = inst & 1, kg = (inst >> 1) & 1, z = inst >> 2;
    const float* A  = g_P + (size_t)(z*LP)*Dm;
    const float* Bm = (uv ? g_Tv : g_Tu) + kg * (Dm*NH*Dm);
    float*       C  = (uv ? g_V : g_U) + (size_t)(z*2 + kg) * (LP*NH*Dm);
    int m0 = blockIdx.y * 64, n0 = blockIdx.x * 128;
    int t = threadIdx.x, lane = t & 31, warp = t >> 5;
    int wm = (warp >> 2)*32, wn = (warp & 3)*32;
    int gr = lane >> 2, gc = lane & 3;
    int ar = t >> 2, aq = (t & 3) << 2;
    int kp = t >> 5, bn = lane << 2;
    float acc[2][4][4] = {};
    float4 pa, pr0, pr1;
    pa  = *(const float4*)&A[(size_t)(m0 + ar)*Dm + aq];
    pr0 = *(const float4*)&Bm[(size_t)(2*kp)*1024 + n0 + bn];
    pr1 = *(const float4*)&Bm[(size_t)(2*kp + 1)*1024 + n0 + bn];
    {
        float pv[4] = {pa.x, pa.y, pa.z, pa.w};
#pragma unroll
        for (int q = 0; q < 2; q++) {
            __half h0,l0,h1,l1;
            split2h(pv[2*q], h0, l0); split2h(pv[2*q+1], h1, l1);
            Ah2[0][((aq>>1)+q)*72 + ar] = mkh2(h0, h1);
            Al2[0][((aq>>1)+q)*72 + ar] = mkh2(l0, l1);
        }
        float v0[4] = {pr0.x,pr0.y,pr0.z,pr0.w};
        float v1[4] = {pr1.x,pr1.y,pr1.z,pr1.w};
#pragma unroll
        for (int q = 0; q < 4; q++) {
            __half h0,l0,h1,l1;
            split2h(v0[q], h0, l0); split2h(v1[q], h1, l1);
            Bh2[0][kp*136 + bn + q] = mkh2(h0, h1);
            Bl2[0][kp*136 + bn + q] = mkh2(l0, l1);
        }
    }
    __syncthreads();
    for (int s = 0; s < 8; s++) {
        int cb = s & 1, nb = cb ^ 1;
        if (s < 7) {
            int k1 = (s + 1) << 4;
            pa  = *(const float4*)&A[(size_t)(m0 + ar)*Dm + k1 + aq];
            pr0 = *(const float4*)&Bm[(size_t)(k1 + 2*kp)*1024 + n0 + bn];
            pr1 = *(const float4*)&Bm[(size_t)(k1 + 2*kp + 1)*1024 + n0 + bn];
        }
        unsigned ah[2][4], al_[2][4], bh[4][2], bl_[4][2];
#pragma unroll
        for (int tm = 0; tm < 2; tm++) {
            int r = wm + tm*16 + gr;
            ah[tm][0] = LDU2(&Ah2[cb][gc*72 + r]);
            ah[tm][1] = LDU2(&Ah2[cb][gc*72 + r + 8]);
            ah[tm][2] = LDU2(&Ah2[cb][(gc+4)*72 + r]);
            ah[tm][3] = LDU2(&Ah2[cb][(gc+4)*72 + r + 8]);
            al_[tm][0] = LDU2(&Al2[cb][gc*72 + r]);
            al_[tm][1] = LDU2(&Al2[cb][gc*72 + r + 8]);
            al_[tm][2] = LDU2(&Al2[cb][(gc+4)*72 + r]);
            al_[tm][3] = LDU2(&Al2[cb][(gc+4)*72 + r + 8]);
        }
#pragma unroll
        for (int tn = 0; tn < 4; tn++) {
            int cn = wn + tn*8 + gr;
            bh[tn][0] = LDU2(&Bh2[cb][gc*136 + cn]);
            bh[tn][1] = LDU2(&Bh2[cb][(gc+4)*136 + cn]);
            bl_[tn][0] = LDU2(&Bl2[cb][gc*136 + cn]);
            bl_[tn][1] = LDU2(&Bl2[cb][(gc+4)*136 + cn]);
        }
#pragma unroll
        for (int tm = 0; tm < 2; tm++)
#pragma unroll
            for (int tn = 0; tn < 4; tn++) {
                mmah(acc[tm][tn], al_[tm], bh[tn]);
                mmah(acc[tm][tn], ah[tm], bl_[tn]);
                mmah(acc[tm][tn], ah[tm], bh[tn]);
            }
        if (s < 7) {
            float pv[4] = {pa.x, pa.y, pa.z, pa.w};
#pragma unroll
            for (int q = 0; q < 2; q++) {
                __half h0,l0,h1,l1;
                split2h(pv[2*q], h0, l0); split2h(pv[2*q+1], h1, l1);
                Ah2[nb][((aq>>1)+q)*72 + ar] = mkh2(h0, h1);
                Al2[nb][((aq>>1)+q)*72 + ar] = mkh2(l0, l1);
            }
            float v0[4] = {pr0.x,pr0.y,pr0.z,pr0.w};
            float v1[4] = {pr1.x,pr1.y,pr1.z,pr1.w};
#pragma unroll
            for (int q = 0; q < 4; q++) {
                __half h0,l0,h1,l1;
                split2h(v0[q], h0, l0); split2h(v1[q], h1, l1);
                Bh2[nb][kp*136 + bn + q] = mkh2(h0, h1);
                Bl2[nb][kp*136 + bn + q] = mkh2(l0, l1);
            }
        }
        __syncthreads();
    }
#pragma unroll
    for (int tm = 0; tm < 2; tm++)
#pragma unroll
        for (int tn = 0; tn < 4; tn++) {
            int r  = m0 + wm + tm*16 + gr;
            int cn = n0 + wn + tn*8 + 2*gc;
            float2 w0; w0.x = acc[tm][tn][0]; w0.y = acc[tm][tn][1];
            float2 w1; w1.x = acc[tm][tn][2]; w1.y = acc[tm][tn][3];
            *(float2*)&C[(size_t)r*1024 + cn]     = w0;
            *(float2*)&C[(size_t)(r+8)*1024 + cn] = w1;
        }
}

// =============== F (fp16 3-term, double-buffered): tile 128x64, warps 4x2 ===============
__global__ __launch_bounds__(256) void gemm_f_kernel() {
    __shared__ __half2 Ah2[2][8*136], Al2[2][8*136];
    __shared__ __half2 Bh2[2][8*72],  Bl2[2][8*72];
    int z = blockIdx.z;
    int m0 = blockIdx.y*128, j0 = blockIdx.x*64;
    int ilo = m0 >> 3;
    int mode = (j0 >= ilo + 16) ? 0 : ((j0 + 64 <= ilo) ? 1 : 2);
    int npass = (mode == 2) ? 2 : 1;
    int t = threadIdx.x, lane = t & 31, warp = t >> 5;
    int wm = (warp >> 1)*32, wn = (warp & 1)*32;
    int gr = lane >> 2, gc = lane & 3;
    int am = t >> 1, ah8 = (t & 1) << 3;
    int jr = t >> 2, bq = (t & 3) << 2;
    const float* Bp = g_P + (size_t)(z*LP)*Dm;
    for (int p = 0; p < npass; p++) {
        int g = (mode == 2) ? p : mode;
        const float* Au = g_U + (size_t)(z*2+g)*(LP*NH*Dm);
        float acc[2][4][4] = {};
        float4 a0, a1, b0;
        a0 = *(const float4*)&Au[(size_t)(m0+am)*Dm + ah8];
        a1 = *(const float4*)&Au[(size_t)(m0+am)*Dm + ah8 + 4];
        b0 = *(const float4*)&Bp[(size_t)(j0+jr)*Dm + bq];
        {
            float av[8] = {a0.x,a0.y,a0.z,a0.w,a1.x,a1.y,a1.z,a1.w};
#pragma unroll
            for (int q = 0; q < 4; q++) {
                __half h0,l0,h1,l1;
                split2h(av[2*q], h0, l0); split2h(av[2*q+1], h1, l1);
                Ah2[0][((ah8>>1)+q)*136 + am] = mkh2(h0, h1);
                Al2[0][((ah8>>1)+q)*136 + am] = mkh2(l0, l1);
            }
            float bv[4] = {b0.x,b0.y,b0.z,b0.w};
#pragma unroll
            for (int q = 0; q < 2; q++) {
                __half h0,l0,h1,l1;
                split2h(bv[2*q], h0, l0); split2h(bv[2*q+1], h1, l1);
                Bh2[0][((bq>>1)+q)*72 + jr] = mkh2(h0, h1);
                Bl2[0][((bq>>1)+q)*72 + jr] = mkh2(l0, l1);
            }
        }
        __syncthreads();
        for (int s = 0; s < 8; s++) {
            int cb = s & 1, nb = cb ^ 1;
            if (s < 7) {
                int k1 = (s + 1) << 4;
                a0 = *(const float4*)&Au[(size_t)(m0+am)*Dm + k1 + ah8];
                a1 = *(const float4*)&Au[(size_t)(m0+am)*Dm + k1 + ah8 + 4];
                b0 = *(const float4*)&Bp[(size_t)(j0+jr)*Dm + k1 + bq];
            }
            unsigned ah[2][4], al_[2][4], bh[4][2], bl_[4][2];
#pragma unroll
            for (int tm = 0; tm < 2; tm++) {
                int r = wm + tm*16 + gr;
                ah[tm][0] = LDU2(&Ah2[cb][gc*136 + r]);
                ah[tm][1] = LDU2(&Ah2[cb][gc*136 + r + 8]);
                ah[tm][2] = LDU2(&Ah2[cb][(gc+4)*136 + r]);
                ah[tm][3] = LDU2(&Ah2[cb][(gc+4)*136 + r + 8]);
                al_[tm][0] = LDU2(&Al2[cb][gc*136 + r]);
                al_[tm][1] = LDU2(&Al2[cb][gc*136 + r + 8]);
                al_[tm][2] = LDU2(&Al2[cb][(gc+4)*136 + r]);
                al_[tm][3] = LDU2(&Al2[cb][(gc+4)*136 + r + 8]);
            }
#pragma unroll
            for (int tn = 0; tn < 4; tn++) {
                int cn = wn + tn*8 + gr;
                bh[tn][0] = LDU2(&Bh2[cb][gc*72 + cn]);
                bh[tn][1] = LDU2(&Bh2[cb][(gc+4)*72 + cn]);
                bl_[tn][0] = LDU2(&Bl2[cb][gc*72 + cn]);
                bl_[tn][1] = LDU2(&Bl2[cb][(gc+4)*72 + cn]);
            }
#pragma unroll
            for (int tm = 0; tm < 2; tm++)
#pragma unroll
                for (int tn = 0; tn < 4; tn++) {
                    mmah(acc[tm][tn], al_[tm], bh[tn]);
                    mmah(acc[tm][tn], ah[tm], bl_[tn]);
                    mmah(acc[tm][tn], ah[tm], bh[tn]);
                }
            if (s < 7) {
                float av[8] = {a0.x,a0.y,a0.z,a0.w,a1.x,a1.y,a1.z,a1.w};
#pragma unroll
                for (int q = 0; q < 4; q++) {
                    __half h0,l0,h1,l1;
                    split2h(av[2*q], h0, l0); split2h(av[2*q+1], h1, l1);
                    Ah2[nb][((ah8>>1)+q)*136 + am] = mkh2(h0, h1);
                    Al2[nb][((ah8>>1)+q)*136 + am] = mkh2(l0, l1);
                }
                float bv[4] = {b0.x,b0.y,b0.z,b0.w};
#pragma unroll
                for (int q = 0; q < 2; q++) {
                    __half h0,l0,h1,l1;
                    split2h(bv[2*q], h0, l0); split2h(bv[2*q+1], h1, l1);
                    Bh2[nb][((bq>>1)+q)*72 + jr] = mkh2(h0, h1);
                    Bl2[nb][((bq>>1)+q)*72 + jr] = mkh2(l0, l1);
                }
            }
            __syncthreads();
        }
#pragma unroll
        for (int tm = 0; tm < 2; tm++)
#pragma unroll
            for (int tn = 0; tn < 4; tn++) {
                int jc = j0 + wn + tn*8 + 2*gc;
#pragma unroll
                for (int half = 0; half < 2; half++) {
                    int m = m0 + wm + tm*16 + gr + half*8;
                    int i = m >> 3, cc = m & 7;
                    size_t off = ((size_t)(z*NH + cc)*LP + i)*LP + jc;
                    float v0 = acc[tm][tn][half*2], v1 = acc[tm][tn][half*2 + 1];
                    if (mode != 2) {
                        float2 w; w.x = v0; w.y = v1;
                        *(float2*)&g_Hmat[off] = w;
                    } else if (p == 0) {
                        float2 w;
                        w.x = (jc     > i) ? v0 : 0.f;
                        w.y = (jc + 1 > i) ? v1 : 0.f;
                        *(float2*)&g_Hmat[off] = w;
                    } else {
                        if (jc     < i) g_Hmat[off]     = v0;
                        if (jc + 1 < i) g_Hmat[off + 1] = v1;
                    }
                }
            }
    }
}

// ---------------- H softmax over j ----------------
__global__ void hsoftmax_kernel() {
    int bid = blockIdx.x;
    int i = bid % Lr;
    int zc = bid / Lr;
    int z = zc >> 3;
    float* row = g_Hmat + (size_t)zc * (LP*LP) + (size_t)i * LP;
    int t = threadIdx.x;
    if (i == 0) {
        for (int j = t; j < Lr; j += 128) row[j] = 0.f;
        return;
    }
    float mi = g_m1[z*LP + i];
    float lv[4];
    float mx = -3.4e38f;
#pragma unroll
    for (int r = 0; r < 4; r++) {
        int j = t + r*128;
        float l = -3.4e38f;
        if (j < Lr) {
            bool ok = (mi != 0.f) && (g_m1[z*LP + j] != 0.f) && (j != i);
            l = ok ? row[j] * 128.f : -1e9f;
        }
        lv[r] = l;
        mx = fmaxf(mx, l);
    }
    __shared__ float shm[4], shs[4];
#pragma unroll
    for (int o = 16; o; o >>= 1) mx = fmaxf(mx, __shfl_xor_sync(0xffffffffu, mx, o));
    if ((t & 31) == 0) shm[t >> 5] = mx;
    __syncthreads();
    mx = fmaxf(fmaxf(shm[0], shm[1]), fmaxf(shm[2], shm[3]));
    float ev[4];
    float s = 0.f;
#pragma unroll
    for (int r = 0; r < 4; r++) {
        int j = t + r*128;
        ev[r] = 0.f;
        if (j < Lr) { ev[r] = __expf(lv[r] - mx); s += ev[r]; }
    }
#pragma unroll
    for (int o = 16; o; o >>= 1) s += __shfl_xor_sync(0xffffffffu, s, o);
    if ((t & 31) == 0) shs[t >> 5] = s;
    __syncthreads();
    s = (shs[0] + shs[1]) + (shs[2] + shs[3]);
    float inv = 1.f / s;
#pragma unroll
    for (int r = 0; r < 4; r++) {
        int j = t + r*128;
        if (j < Lr) row[j] = ev[r] * inv;
    }
}

// =============== G+Hm merged (fp16 3-term, double-buffered, 32 flat stages) ===============
__global__ __launch_bounds__(256) void gemm_gh_kernel() {
    __shared__ __half2 Ah2[2][8*72],  Al2[2][8*72];
    __shared__ __half2 Bh2[2][8*136], Bl2[2][8*136];
    int kind = blockIdx.x & 1;          // 0 = G, 1 = Hm
    int c = blockIdx.x >> 1;
    int z = blockIdx.z;
    const float* Hmp = g_Hmat + (size_t)(z*NH + c)*(LP*LP);
    int t = threadIdx.x, lane = t & 31, warp = t >> 5;
    int wm = (warp >> 2)*32, wn = (warp & 3)*32;
    int gr = lane >> 2, gc = lane & 3;
    float acc[2][4][4] = {};
    if (kind == 0) {
        // ---------- G: C[i 64 x a 128] = Hsel @ V ----------
        int i0 = blockIdx.y*64;
        int ir = t >> 2, jq = (t & 3) << 2;
        int jp = t >> 5, bn = lane << 2;
        int c0 = i0 >> 4;
        float4 hv; float4 v0, v1;
        int nss, np, nmode;
#define G_MAP(f, ss, p, md) \
        if ((f) < c0) { ss = (f); p = 0; md = 1; } \
        else if ((f) < c0 + 8) { ss = c0 + (((f) - c0) >> 1); p = ((f) - c0) & 1; md = 2; } \
        else { ss = (f) - 4; p = 0; md = 0; }
        {
            G_MAP(0, nss, np, nmode)
            int gg = (nmode == 2) ? np : nmode;
            int j0s = nss << 4;
            hv = *(const float4*)&Hmp[(size_t)(i0 + ir)*LP + j0s + jq];
            const float* Vp = g_V + (size_t)(z*2+gg)*(LP*NH*Dm) + (size_t)c*Dm;
            v0 = *(const float4*)&Vp[(size_t)(j0s + 2*jp)*1024 + bn];
            v1 = *(const float4*)&Vp[(size_t)(j0s + 2*jp + 1)*1024 + bn];
            int ig = i0 + ir;
            float h4[4] = {hv.x, hv.y, hv.z, hv.w};
            float mv[4];
#pragma unroll
            for (int q = 0; q < 4; q++) {
                float val = h4[q];
                if (nmode == 2) {
                    int jg = j0s + jq + q;
                    bool keep = (gg == 0) ? (jg > ig) : (jg < ig);
                    if (!keep) val = 0.f;
                }
                mv[q] = val;
            }
#pragma unroll
            for (int q = 0; q < 2; q++) {
                __half h0,l0,h1,l1;
                split2h(mv[2*q], h0, l0); split2h(mv[2*q+1], h1, l1);
                Ah2[0][((jq>>1)+q)*72 + ir] = mkh2(h0, h1);
                Al2[0][((jq>>1)+q)*72 + ir] = mkh2(l0, l1);
            }
            float r0[4] = {v0.x,v0.y,v0.z,v0.w};
            float r1[4] = {v1.x,v1.y,v1.z,v1.w};
#pragma unroll
            for (int q = 0; q < 4; q++) {
                __half h0,l0,h1,l1;
                split2h(r0[q], h0, l0); split2h(r1[q], h1, l1);
                Bh2[0][jp*136 + bn + q] = mkh2(h0, h1);
                Bl2[0][jp*136 + bn + q] = mkh2(l0, l1);
            }
        }
        __syncthreads();
        for (int f = 0; f < 32; f++) {
            int cb = f & 1, nb = cb ^ 1;
            int gg = 0, j0s = 0;
            if (f + 1 < 32) {
                G_MAP(f + 1, nss, np, nmode)
                gg = (nmode == 2) ? np : nmode;
                j0s = nss << 4;
                hv = *(const float4*)&Hmp[(size_t)(i0 + ir)*LP + j0s + jq];
                const float* Vp = g_V + (size_t)(z*2+gg)*(LP*NH*Dm) + (size_t)c*Dm;
                v0 = *(const float4*)&Vp[(size_t)(j0s + 2*jp)*1024 + bn];
                v1 = *(const float4*)&Vp[(size_t)(j0s + 2*jp + 1)*1024 + bn];
            }
            unsigned ah[2][4], al_[2][4], bh[4][2], bl_[4][2];
#pragma unroll
            for (int tm = 0; tm < 2; tm++) {
                int r = wm + tm*16 + gr;
                ah[tm][0] = LDU2(&Ah2[cb][gc*72 + r]);
                ah[tm][1] = LDU2(&Ah2[cb][gc*72 + r + 8]);
                ah[tm][2] = LDU2(&Ah2[cb][(gc+4)*72 + r]);
                ah[tm][3] = LDU2(&Ah2[cb][(gc+4)*72 + r + 8]);
                al_[tm][0] = LDU2(&Al2[cb][gc*72 + r]);
                al_[tm][1] = LDU2(&Al2[cb][gc*72 + r + 8]);
                al_[tm][2] = LDU2(&Al2[cb][(gc+4)*72 + r]);
                al_[tm][3] = LDU2(&Al2[cb][(gc+4)*72 + r + 8]);
            }
#pragma unroll
            for (int tn = 0; tn < 4; tn++) {
                int cn = wn + tn*8 + gr;
                bh[tn][0] = LDU2(&Bh2[cb][gc*136 + cn]);
                bh[tn][1] = LDU2(&Bh2[cb][(gc+4)*136 + cn]);
                bl_[tn][0] = LDU2(&Bl2[cb][gc*136 + cn]);
                bl_[tn][1] = LDU2(&Bl2[cb][(gc+4)*136 + cn]);
            }
#pragma unroll
            for (int tm = 0; tm < 2; tm++)
#pragma unroll
                for (int tn = 0; tn < 4; tn++) {
                    mmah(acc[tm][tn], al_[tm], bh[tn]);
                    mmah(acc[tm][tn], ah[tm], bl_[tn]);
                    mmah(acc[tm][tn], ah[tm], bh[tn]);
                }
            if (f + 1 < 32) {
                int ig = i0 + ir;
                float h4[4] = {hv.x, hv.y, hv.z, hv.w};
                float mv[4];
#pragma unroll
                for (int q = 0; q < 4; q++) {
                    float val = h4[q];
                    if (nmode == 2) {
                        int jg = j0s + jq + q;
                        bool keep = (gg == 0) ? (jg > ig) : (jg < ig);
                        if (!keep) val = 0.f;
                    }
                    mv[q] = val;
                }
#pragma unroll
                for (int q = 0; q < 2; q++) {
                    __half h0,l0,h1,l1;
                    split2h(mv[2*q], h0, l0); split2h(mv[2*q+1], h1, l1);
                    Ah2[nb][((jq>>1)+q)*72 + ir] = mkh2(h0, h1);
                    Al2[nb][((jq>>1)+q)*72 + ir] = mkh2(l0, l1);
                }
                float r0[4] = {v0.x,v0.y,v0.z,v0.w};
                float r1[4] = {v1.x,v1.y,v1.z,v1.w};
#pragma unroll
                for (int q = 0; q < 4; q++) {
                    __half h0,l0,h1,l1;
                    split2h(r0[q], h0, l0); split2h(r1[q], h1, l1);
                    Bh2[nb][jp*136 + bn + q] = mkh2(h0, h1);
                    Bl2[nb][jp*136 + bn + q] = mkh2(l0, l1);
                }
            }
            __syncthreads();
        }
#undef G_MAP
        float* out = &g_Gp[((size_t)(z*NH + c)*LP + i0)*Dm];
#pragma unroll
        for (int tm = 0; tm < 2; tm++)
#pragma unroll
            for (int tn = 0; tn < 4; tn++) {
                int r  = wm + tm*16 + gr;
                int cn = wn + tn*8 + 2*gc;
                float2 w0; w0.x = acc[tm][tn][0]; w0.y = acc[tm][tn][1];
                float2 w1; w1.x = acc[tm][tn][2]; w1.y = acc[tm][tn][3];
                *(float2*)&out[(size_t)r*Dm + cn]     = w0;
                *(float2*)&out[(size_t)(r+8)*Dm + cn] = w1;
            }
    } else {
        // ---------- Hm: C[j 64 x b 128] = Hsel^T @ U ----------
        int j0 = blockIdx.y*64;
        int ip = t >> 5, jc2 = lane << 1;
        int bn = lane << 2;
        int c0 = j0 >> 4;
        float2 hr0, hr1; float4 u0, u1;
        int nss, np, nmode;
#define H_MAP(f, ss, p, md) \
        if ((f) < c0) { ss = (f); p = 0; md = 0; } \
        else if ((f) < c0 + 8) { ss = c0 + (((f) - c0) >> 1); p = ((f) - c0) & 1; md = 2; } \
        else { ss = (f) - 4; p = 0; md = 1; }
        {
            H_MAP(0, nss, np, nmode)
            int gg = (nmode == 2) ? np : nmode;
            int i0s = nss << 4;
            int ig0 = i0s + 2*ip, ig1 = ig0 + 1;
            hr0 = *(const float2*)&Hmp[(size_t)ig0*LP + j0 + jc2];
            hr1 = *(const float2*)&Hmp[(size_t)ig1*LP + j0 + jc2];
            const float* Up = g_U + (size_t)(z*2+gg)*(LP*NH*Dm) + (size_t)c*Dm;
            u0 = *(const float4*)&Up[(size_t)(i0s + 2*ip)*1024 + bn];
            u1 = *(const float4*)&Up[(size_t)(i0s + 2*ip + 1)*1024 + bn];
            float a00 = hr0.x, a01 = hr0.y, a10 = hr1.x, a11 = hr1.y;
            if (nmode == 2) {
                int jg0 = j0 + jc2, jg1 = jg0 + 1;
                if (!((gg == 0) ? (ig0 < jg0) : (ig0 > jg0))) a00 = 0.f;
                if (!((gg == 0) ? (ig0 < jg1) : (ig0 > jg1))) a01 = 0.f;
                if (!((gg == 0) ? (ig1 < jg0) : (ig1 > jg0))) a10 = 0.f;
                if (!((gg == 0) ? (ig1 < jg1) : (ig1 > jg1))) a11 = 0.f;
            }
            __half h00,l00,h01,l01,h10,l10,h11,l11;
            split2h(a00, h00, l00); split2h(a01, h01, l01);
            split2h(a10, h10, l10); split2h(a11, h11, l11);
            Ah2[0][ip*72 + jc2]     = mkh2(h00, h10);
            Ah2[0][ip*72 + jc2 + 1] = mkh2(h01, h11);
            Al2[0][ip*72 + jc2]     = mkh2(l00, l10);
            Al2[0][ip*72 + jc2 + 1] = mkh2(l01, l11);
            float r0[4] = {u0.x,u0.y,u0.z,u0.w};
            float r1[4] = {u1.x,u1.y,u1.z,u1.w};
#pragma unroll
            for (int q = 0; q < 4; q++) {
                __half h0,l0,h1,l1;
                split2h(r0[q], h0, l0); split2h(r1[q], h1, l1);
                Bh2[0][ip*136 + bn + q] = mkh2(h0, h1);
                Bl2[0][ip*136 + bn + q] = mkh2(l0, l1);
            }
        }
        __syncthreads();
        for (int f = 0; f < 32; f++) {
            int cb = f & 1, nb = cb ^ 1;
            int gg = 0, i0s = 0;
            if (f + 1 < 32) {
                H_MAP(f + 1, nss, np, nmode)
                gg = (nmode == 2) ? np : nmode;
                i0s = nss << 4;
                int ig0 = i0s + 2*ip, ig1 = ig0 + 1;
                hr0 = *(const float2*)&Hmp[(size_t)ig0*LP + j0 + jc2];
                hr1 = *(const float2*)&Hmp[(size_t)ig1*LP + j0 + jc2];
                const float* Up = g_U + (size_t)(z*2+gg)*(LP*NH*Dm) + (size_t)c*Dm;
                u0 = *(const float4*)&Up[(size_t)(i0s + 2*ip)*1024 + bn];
                u1 = *(const float4*)&Up[(size_t)(i0s + 2*ip + 1)*1024 + bn];
            }
            unsigned ah[2][4], al_[2][4], bh[4][2], bl_[4][2];
#pragma unroll
            for (int tm = 0; tm < 2; tm++) {
                int r = wm + tm*16 + gr;
                ah[tm][0] = LDU2(&Ah2[cb][gc*72 + r]);
                ah[tm][1] = LDU2(&Ah2[cb][gc*72 + r + 8]);
                ah[tm][2] = LDU2(&Ah2[cb][(gc+4)*72 + r]);
                ah[tm][3] = LDU2(&Ah2[cb][(gc+4)*72 + r + 8]);
                al_[tm][0] = LDU2(&Al2[cb][gc*72 + r]);
                al_[tm][1] = LDU2(&Al2[cb][gc*72 + r + 8]);
                al_[tm][2] = LDU2(&Al2[cb][(gc+4)*72 + r]);
                al_[tm][3] = LDU2(&Al2[cb][(gc+4)*72 + r + 8]);
            }
#pragma unroll
            for (int tn = 0; tn < 4; tn++) {
                int cn = wn + tn*8 + gr;
                bh[tn][0] = LDU2(&Bh2[cb][gc*136 + cn]);
                bh[tn][1] = LDU2(&Bh2[cb][(gc+4)*136 + cn]);
                bl_[tn][0] = LDU2(&Bl2[cb][gc*136 + cn]);
                bl_[tn][1] = LDU2(&Bl2[cb][(gc+4)*136 + cn]);
            }
#pragma unroll
            for (int tm = 0; tm < 2; tm++)
#pragma unroll
                for (int tn = 0; tn < 4; tn++) {
                    mmah(acc[tm][tn], al_[tm], bh[tn]);
                    mmah(acc[tm][tn], ah[tm], bl_[tn]);
                    mmah(acc[tm][tn], ah[tm], bh[tn]);
                }
            if (f + 1 < 32) {
                int ig0 = i0s + 2*ip, ig1 = ig0 + 1;
                float a00 = hr0.x, a01 = hr0.y, a10 = hr1.x, a11 = hr1.y;
                if (nmode == 2) {
                    int jg0 = j0 + jc2, jg1 = jg0 + 1;
                    if (!((gg == 0) ? (ig0 < jg0) : (ig0 > jg0))) a00 = 0.f;
                    if (!((gg == 0) ? (ig0 < jg1) : (ig0 > jg1))) a01 = 0.f;
                    if (!((gg == 0) ? (ig1 < jg0) : (ig1 > jg0))) a10 = 0.f;
                    if (!((gg == 0) ? (ig1 < jg1) : (ig1 > jg1))) a11 = 0.f;
                }
                __half h00,l00,h01,l01,h10,l10,h11,l11;
                split2h(a00, h00, l00); split2h(a01, h01, l01);
                split2h(a10, h10, l10); split2h(a11, h11, l11);
                Ah2[nb][ip*72 + jc2]     = mkh2(h00, h10);
                Ah2[nb][ip*72 + jc2 + 1] = mkh2(h01, h11);
                Al2[nb][ip*72 + jc2]     = mkh2(l00, l10);
                Al2[nb][ip*72 + jc2 + 1] = mkh2(l01, l11);
                float r0[4] = {u0.x,u0.y,u0.z,u0.w};
                float r1[4] = {u1.x,u1.y,u1.z,u1.w};
#pragma unroll
                for (int q = 0; q < 4; q++) {
                    __half h0,l0,h1,l1;
                    split2h(r0[q], h0, l0); split2h(r1[q], h1, l1);
                    Bh2[nb][ip*136 + bn + q] = mkh2(h0, h1);
                    Bl2[nb][ip*136 + bn + q] = mkh2(l0, l1);
                }
            }
            __syncthreads();
        }
#undef H_MAP
        float* out = &g_Hp[((size_t)(z*NH + c)*LP + j0)*Dm];
#pragma unroll
        for (int tm = 0; tm < 2; tm++)
#pragma unroll
            for (int tn = 0; tn < 4; tn++) {
                int r  = wm + tm*16 + gr;
                int cn = wn + tn*8 + 2*gc;
                float2 w0; w0.x = acc[tm][tn][0]; w0.y = acc[tm][tn][1];
                float2 w1; w1.x = acc[tm][tn][2]; w1.y = acc[tm][tn][3];
                *(float2*)&out[(size_t)r*Dm + cn]     = w0;
                *(float2*)&out[(size_t)(r+8)*Dm + cn] = w1;
            }
    }
}

// ---------------- final reduce (writes qz for output) ----------------
__global__ void reduce_qz_kernel() {
    int idx = blockIdx.x * blockDim.x + threadIdx.x;
    if (idx >= Bz*LP*Dm) return;
    int d = idx & 127;
    int zi = idx >> 7;
    int i = zi % LP, z = zi / LP;
    float s = g_unary[idx];
#pragma unroll
    for (int c = 0; c < NH; c++) {
        size_t o = ((size_t)(z*NH + c)*LP + i)*Dm + d;
        s += g_Gp[o] + g_Hp[o];
    }
    g_qz[idx] = s * g_m1[zi];
}

__global__ void out_kernel(float* __restrict__ out) {
    int idx = blockIdx.x * blockDim.x + threadIdx.x;
    if (idx >= Bz*L0c*Dm) return;
    int d = idx & 127;
    int zt = idx >> 7;
    int tt = zt % L0c, z = zt / L0c;
    out[idx] = g_qz[(z*LP + 1 + tt)*Dm + d];
}

extern "C" void kernel_launch(void* const* d_in, const int* in_sizes, int n_in,
                              void* d_out, int out_size) {
    const float* x = nullptr;
    const float* mask = nullptr;
    const float* tern = nullptr;
    for (int i = 0; i < n_in; i++) {
        if (in_sizes[i] == Bz*L0c*Dm)       x    = (const float*)d_in[i];
        else if (in_sizes[i] == Bz*L0c)     mask = (const float*)d_in[i];
        else if (in_sizes[i] == 2*Dm*Dm*NH) tern = (const float*)d_in[i];
    }
    if (!x || !mask || !tern) return;

    prep_unary_kernel<<<(Bz*LP*Dm + 255)/256, 256>>>(x, mask);
    zero_ppad_kernel<<<(128*Dm + 255)/256, 256>>>();
    prep_T_kernel<<<(2*Dm*Dm*NH + 255)/256, 256>>>(tern);

    softmax_p_kernel<<<Bz*Lr, 128>>>();
    for (int it = 0; it < NIT; it++) {
        gemm_uv_kernel<<<dim3(8, 7, 32), 256>>>();
        gemm_f_kernel<<<dim3(7, 28, Bz), 256>>>();
        hsoftmax_kernel<<<Bz*NH*Lr, 128>>>();
        gemm_gh_kernel<<<dim3(NH*2, 7, Bz), 256>>>();
        if (it < NIT - 1) {
            reduce_softmax_kernel<<<Bz*Lr, 128>>>();
        } else {
            reduce_qz_kernel<<<(Bz*LP*Dm + 255)/256, 256>>>();
        }
    }
    out_kernel<<<(Bz*L0c*Dm + 255)/256, 256>>>((float*)d_out);
}